// round 2
// baseline (speedup 1.0000x reference)
#include <cuda_runtime.h>
#include <cuda_bf16.h>
#include <math.h>

#define BATCH 64
#define SEQ   512
#define EMB   128
#define HID   256
#define H4    1024
#define TAGS  9

// static scratch (no runtime allocation)
__device__ float g_xz[2][SEQ][BATCH][H4];          // per-direction xz[t][b][1024]
__device__ float g_h[2][2][8][8][HID];             // [buf][dir][bblock][row][unit]
__device__ float g_hall[BATCH * SEQ * 2 * HID];    // [b*S+t][h_fwd|h_bwd]

__device__ __forceinline__ float sigmoid_f(float x) {
    return __fdividef(1.0f, 1.0f + __expf(-x));
}
__device__ __forceinline__ float tanh_f(float x) {
    return 1.0f - __fdividef(2.0f, __expf(2.0f * x) + 1.0f);
}

// ---------------------------------------------------------------------------
// Phase 1: xz = emb[text] @ [W_f|W_b] + bias.  M=32768, N=2048, K=128
// ---------------------------------------------------------------------------
__global__ __launch_bounds__(256) void gemm_xz_kernel(
    const int* __restrict__ text, const float* __restrict__ emb,
    const float* __restrict__ Wf, const float* __restrict__ Wb,
    const float* __restrict__ bf, const float* __restrict__ bb)
{
    __shared__ float As[16][128];
    __shared__ float Ws[16][64];
    __shared__ int   toks[128];

    const int m0 = blockIdx.y * 128;
    const int n0 = blockIdx.x * 64;
    const int tid = threadIdx.x;

    if (tid < 128) toks[tid] = text[m0 + tid];
    __syncthreads();

    const float* W = (n0 < H4) ? Wf : Wb;
    const int nw0 = n0 & (H4 - 1);
    const int tx = tid & 15;
    const int ty = tid >> 4;

    float acc[8][4];
#pragma unroll
    for (int i = 0; i < 8; i++)
#pragma unroll
        for (int j = 0; j < 4; j++) acc[i][j] = 0.0f;

    for (int k0 = 0; k0 < EMB; k0 += 16) {
#pragma unroll
        for (int q = 0; q < 2; q++) {
            int id = tid * 2 + q;
            int row = id >> 2, kq = id & 3;
            float4 v = *reinterpret_cast<const float4*>(&emb[toks[row] * EMB + k0 + kq * 4]);
            As[kq * 4 + 0][row] = v.x;
            As[kq * 4 + 1][row] = v.y;
            As[kq * 4 + 2][row] = v.z;
            As[kq * 4 + 3][row] = v.w;
        }
        {
            int k = tid >> 4, n4 = (tid & 15) * 4;
            *reinterpret_cast<float4*>(&Ws[k][n4]) =
                *reinterpret_cast<const float4*>(&W[(k0 + k) * H4 + nw0 + n4]);
        }
        __syncthreads();

#pragma unroll
        for (int k = 0; k < 16; k++) {
            float4 a0 = *reinterpret_cast<const float4*>(&As[k][ty * 8]);
            float4 a1 = *reinterpret_cast<const float4*>(&As[k][ty * 8 + 4]);
            float4 w4 = *reinterpret_cast<const float4*>(&Ws[k][tx * 4]);
            float a[8] = {a0.x, a0.y, a0.z, a0.w, a1.x, a1.y, a1.z, a1.w};
            float w[4] = {w4.x, w4.y, w4.z, w4.w};
#pragma unroll
            for (int i = 0; i < 8; i++)
#pragma unroll
                for (int j = 0; j < 4; j++) acc[i][j] += a[i] * w[j];
        }
        __syncthreads();
    }

    const float* bias = (n0 < H4) ? bf : bb;
    const int d = (n0 < H4) ? 0 : 1;
    const int col = nw0 + tx * 4;
    float4 bv = *reinterpret_cast<const float4*>(&bias[col]);

#pragma unroll
    for (int i = 0; i < 8; i++) {
        int gm = m0 + ty * 8 + i;
        int b = gm >> 9, t = gm & (SEQ - 1);
        float4 v;
        v.x = acc[i][0] + bv.x;
        v.y = acc[i][1] + bv.y;
        v.z = acc[i][2] + bv.z;
        v.w = acc[i][3] + bv.w;
        *reinterpret_cast<float4*>(&g_xz[d][t][b][col]) = v;
    }
}

// ---------------------------------------------------------------------------
// Phase 2: persistent bidirectional LSTM. 16 clusters x 8 CTAs (128 SMs).
// cluster = (dir, batch-block of 8 rows); rank = 128-gate-column block.
// ---------------------------------------------------------------------------
#define UT_PAD 260
#define LSTM_SMEM ((128 * UT_PAD + 8 * 256 + 8 * 128) * 4)

__global__ void __cluster_dims__(8, 1, 1) __launch_bounds__(256, 1)
lstm_kernel(const float* __restrict__ Uf, const float* __restrict__ Ub)
{
    extern __shared__ float smem[];
    float* Ut  = smem;                 // [128][UT_PAD] transposed U slice
    float* hsh = Ut + 128 * UT_PAD;    // [8][256] current h
    float* zsh = hsh + 8 * 256;        // [8][128] z partial

    const int tid = threadIdx.x;
    const int cb  = blockIdx.x & 7;    // cluster rank = column block
    const int cid = blockIdx.x >> 3;
    const int d   = cid >> 3;          // direction
    const int bb  = cid & 7;           // batch block
    const float* U = d ? Ub : Uf;

    // resident transposed U slice: Ut[cc][k] = U[k][gate(cc)*256 + cb*32 + u(cc)]
    for (int i = tid; i < 128 * 256; i += 256) {
        int cc = i & 127, k = i >> 7;
        int gcol = ((cc >> 5) << 8) + (cb << 5) + (cc & 31);
        Ut[cc * UT_PAD + k] = U[k * H4 + gcol];
    }
    // zero this CTA's h slice for buffer 0
    {
        int rB = tid >> 5, uB = tid & 31;
        g_h[0][d][bb][rB][(cb << 5) + uB] = 0.0f;
    }
    __syncthreads();
    asm volatile("barrier.cluster.arrive.aligned;" ::: "memory");
    asm volatile("barrier.cluster.wait.aligned;" ::: "memory");

    const int w = tid >> 5, lane = tid & 31;
    const int r0 = (w & 1) * 4;                 // GEMM rows
    const int colA = ((w >> 1) << 5) + lane;    // GEMM column (cc index)
    const float* UtCol = &Ut[colA * UT_PAD];

    const int rB = tid >> 5;                    // gate-phase row
    const int uB = lane;                        // gate-phase unit
    const int bglob = bb * 8 + rB;
    float c = 0.0f;
    int cur = 0;

    for (int t = 0; t < SEQ; t++) {
        const int tt = d ? (SEQ - 1 - t) : t;

        // stage h (all 256 units, 8 rows) from global into shared
        {
            const float* hp = &g_h[cur][d][bb][0][0];
#pragma unroll
            for (int q = 0; q < 2; q++) {
                int idx = (tid + q * 256) * 4;
                *reinterpret_cast<float4*>(&hsh[idx]) =
                    *reinterpret_cast<const float4*>(&hp[idx]);
            }
        }
        // prefetch xz for this thread's 4 gates
        const float* xzp = &g_xz[d][tt][bglob][(cb << 5) + uB];
        const float xi = __ldg(xzp);
        const float xf = __ldg(xzp + 256);
        const float xg = __ldg(xzp + 512);
        const float xo = __ldg(xzp + 768);
        __syncthreads();

        // z[r0..r0+3][colA] = sum_k h[r][k] * Ut[colA][k]
        float a0 = 0.f, a1 = 0.f, a2 = 0.f, a3 = 0.f;
        const float* hp = &hsh[r0 * 256];
#pragma unroll 8
        for (int k4 = 0; k4 < 64; k4++) {
            float4 u4 = *reinterpret_cast<const float4*>(&UtCol[k4 * 4]);
            float4 h0 = *reinterpret_cast<const float4*>(&hp[0 * 256 + k4 * 4]);
            float4 h1 = *reinterpret_cast<const float4*>(&hp[1 * 256 + k4 * 4]);
            float4 h2 = *reinterpret_cast<const float4*>(&hp[2 * 256 + k4 * 4]);
            float4 h3 = *reinterpret_cast<const float4*>(&hp[3 * 256 + k4 * 4]);
            a0 += u4.x * h0.x; a1 += u4.x * h1.x; a2 += u4.x * h2.x; a3 += u4.x * h3.x;
            a0 += u4.y * h0.y; a1 += u4.y * h1.y; a2 += u4.y * h2.y; a3 += u4.y * h3.y;
            a0 += u4.z * h0.z; a1 += u4.z * h1.z; a2 += u4.z * h2.z; a3 += u4.z * h3.z;
            a0 += u4.w * h0.w; a1 += u4.w * h1.w; a2 += u4.w * h2.w; a3 += u4.w * h3.w;
        }
        zsh[(r0 + 0) * 128 + colA] = a0;
        zsh[(r0 + 1) * 128 + colA] = a1;
        zsh[(r0 + 2) * 128 + colA] = a2;
        zsh[(r0 + 3) * 128 + colA] = a3;
        __syncthreads();

        // gates: thread -> (row rB, unit uB)
        const float zi = zsh[rB * 128 +  0 + uB] + xi;
        const float zf = zsh[rB * 128 + 32 + uB] + xf;
        const float zg = zsh[rB * 128 + 64 + uB] + xg;
        const float zo = zsh[rB * 128 + 96 + uB] + xo;
        const float ig = sigmoid_f(zi);
        const float fg = sigmoid_f(zf);
        const float gg = tanh_f(zg);
        const float og = sigmoid_f(zo);
        c = fg * c + ig * gg;
        const float h = og * tanh_f(c);

        const int nxt = cur ^ 1;
        g_h[nxt][d][bb][rB][(cb << 5) + uB] = h;
        g_hall[(bglob * SEQ + tt) * (2 * HID) + d * HID + (cb << 5) + uB] = h;

        asm volatile("barrier.cluster.arrive.aligned;" ::: "memory");
        asm volatile("barrier.cluster.wait.aligned;" ::: "memory");
        cur = nxt;
    }
}

// ---------------------------------------------------------------------------
// Phase 3: logits = h_all @ W_d + b_d   (warp per row-group)
// ---------------------------------------------------------------------------
__global__ __launch_bounds__(256) void decoder_kernel(
    const float* __restrict__ Wd, const float* __restrict__ bd,
    float* __restrict__ out)
{
    __shared__ float Ws[2 * HID * TAGS];
    __shared__ float bs[TAGS];
    const int tid = threadIdx.x;
    for (int i = tid; i < 2 * HID * TAGS; i += 256) Ws[i] = Wd[i];
    if (tid < TAGS) bs[tid] = bd[tid];
    __syncthreads();

    const int w = tid >> 5, lane = tid & 31;
    const int wg = blockIdx.x * 8 + w;

    for (int rr = 0; rr < 16; rr++) {
        const int row = wg * 16 + rr;
        const float* hp = &g_hall[row * (2 * HID)];
        float p[TAGS];
#pragma unroll
        for (int j = 0; j < TAGS; j++) p[j] = 0.0f;
#pragma unroll
        for (int e = 0; e < 16; e++) {
            const int k = e * 32 + lane;
            const float hv = __ldg(&hp[k]);
#pragma unroll
            for (int j = 0; j < TAGS; j++) p[j] += hv * Ws[k * TAGS + j];
        }
#pragma unroll
        for (int j = 0; j < TAGS; j++)
#pragma unroll
            for (int off = 16; off; off >>= 1)
                p[j] += __shfl_xor_sync(0xffffffffu, p[j], off);
        if (lane < TAGS) out[row * TAGS + lane] = p[lane] + bs[lane];
    }
}

// ---------------------------------------------------------------------------
// Phase 4: lens + CRF sequence score + CRF log-norm.  One warp per batch row.
// ---------------------------------------------------------------------------
__global__ __launch_bounds__(32) void crf_kernel(
    const int* __restrict__ text, const int* __restrict__ labels,
    const float* __restrict__ trans, const float* __restrict__ logits,
    float* __restrict__ out_lens, float* __restrict__ out_ll)
{
    __shared__ float lg[SEQ * TAGS];
    __shared__ int   lb[SEQ];
    __shared__ float tr[TAGS * TAGS];

    const int b = blockIdx.x;
    const int lane = threadIdx.x;
    const float* Lp = logits + b * SEQ * TAGS;

    for (int i = lane; i < SEQ * TAGS; i += 32) lg[i] = Lp[i];
    for (int i = lane; i < SEQ; i += 32) lb[i] = labels[b * SEQ + i];
    for (int i = lane; i < TAGS * TAGS; i += 32) tr[i] = trans[i];

    int cnt = 0;
    for (int t = lane; t < SEQ; t += 32) cnt += (text[b * SEQ + t] != 0);
#pragma unroll
    for (int off = 16; off; off >>= 1) cnt += __shfl_xor_sync(0xffffffffu, cnt, off);
    __syncthreads();
    const int len = cnt;

    float uny = 0.0f, bny = 0.0f;
    for (int t = lane; t < SEQ; t += 32)
        if (t < len) uny += lg[t * TAGS + lb[t]];
    for (int t = lane; t < SEQ - 1; t += 32)
        if (t < len - 1) bny += tr[lb[t] * TAGS + lb[t + 1]];
#pragma unroll
    for (int off = 16; off; off >>= 1) {
        uny += __shfl_xor_sync(0xffffffffu, uny, off);
        bny += __shfl_xor_sync(0xffffffffu, bny, off);
    }

    // forward algorithm, tag j = lane (lanes >= TAGS mirror j=TAGS-1, masked out later)
    const int j = (lane < TAGS) ? lane : (TAGS - 1);
    float Tc[TAGS];
#pragma unroll
    for (int i = 0; i < TAGS; i++) Tc[i] = tr[i * TAGS + j];

    float a = lg[j];   // alpha0 = logits[:,0]
    for (int t = 1; t < SEQ; t++) {
        float ai[TAGS];
#pragma unroll
        for (int i = 0; i < TAGS; i++) ai[i] = __shfl_sync(0xffffffffu, a, i);
        if (t < len) {
            float m = -1e30f;
#pragma unroll
            for (int i = 0; i < TAGS; i++) m = fmaxf(m, ai[i] + Tc[i]);
            float s = 0.0f;
#pragma unroll
            for (int i = 0; i < TAGS; i++) s += __expf(ai[i] + Tc[i] - m);
            a = m + __logf(s) + lg[t * TAGS + j];
        }
    }
    // logsumexp over tags
    float av = (lane < TAGS) ? a : -1e30f;
    float m = av;
#pragma unroll
    for (int off = 16; off; off >>= 1) m = fmaxf(m, __shfl_xor_sync(0xffffffffu, m, off));
    float s = (lane < TAGS) ? __expf(av - m) : 0.0f;
#pragma unroll
    for (int off = 16; off; off >>= 1) s += __shfl_xor_sync(0xffffffffu, s, off);
    const float logZ = m + __logf(s);

    if (lane == 0) {
        out_lens[b] = (float)len;
        out_ll[b]   = uny + bny - logZ;
    }
}

// ---------------------------------------------------------------------------
extern "C" void kernel_launch(void* const* d_in, const int* in_sizes, int n_in,
                              void* d_out, int out_size) {
    const int*   text   = (const int*)  d_in[0];
    const int*   labels = (const int*)  d_in[1];
    const float* emb    = (const float*)d_in[2];
    const float* W_f    = (const float*)d_in[3];
    const float* U_f    = (const float*)d_in[4];
    const float* b_f    = (const float*)d_in[5];
    const float* W_b    = (const float*)d_in[6];
    const float* U_b    = (const float*)d_in[7];
    const float* b_b    = (const float*)d_in[8];
    const float* W_d    = (const float*)d_in[9];
    const float* b_d    = (const float*)d_in[10];
    const float* trans  = (const float*)d_in[11];
    float* out = (float*)d_out;

    static bool attr_done = false;
    if (!attr_done) {
        cudaFuncSetAttribute(lstm_kernel,
                             cudaFuncAttributeMaxDynamicSharedMemorySize, LSTM_SMEM);
        attr_done = true;
    }

    gemm_xz_kernel<<<dim3(32, 256), 256>>>(text, emb, W_f, W_b, b_f, b_b);
    lstm_kernel<<<128, 256, LSTM_SMEM>>>(U_f, U_b);
    decoder_kernel<<<256, 256>>>(W_d, b_d, out);

    float* out_logits = out;                         // B*S*TAGS = 294912
    float* out_lens   = out + BATCH * SEQ * TAGS;    // 64
    float* out_ll     = out_lens + BATCH;            // 64
    crf_kernel<<<BATCH, 32>>>(text, labels, trans, out_logits, out_lens, out_ll);
}

// round 3
// speedup vs baseline: 1.0572x; 1.0572x over previous
#include <cuda_runtime.h>
#include <cuda_bf16.h>
#include <math.h>

#define BATCH 64
#define SEQ   512
#define EMB   128
#define HID   256
#define H4    1024
#define TAGS  9

// static scratch (no runtime allocation)
__device__ float g_xz[2][SEQ][BATCH][H4];          // per-direction xz[t][b][1024]
__device__ float g_hall[BATCH * SEQ * 2 * HID];    // [b*S+t][h_fwd|h_bwd]

__device__ __forceinline__ float sigmoid_f(float x) {
    return __fdividef(1.0f, 1.0f + __expf(-x));
}
__device__ __forceinline__ float tanh_f(float x) {
    return 1.0f - __fdividef(2.0f, __expf(2.0f * x) + 1.0f);
}
// packed fp32x2 FMA: a += b * c elementwise on 2 packed floats (Blackwell FFMA2)
__device__ __forceinline__ void fma2(unsigned long long& a, unsigned long long b,
                                     unsigned long long c) {
    asm("fma.rn.f32x2 %0, %1, %2, %0;" : "+l"(a) : "l"(b), "l"(c));
}
__device__ __forceinline__ unsigned long long dupf2(float x) {
    unsigned long long r;
    unsigned u = __float_as_uint(x);
    asm("mov.b64 %0, {%1, %1};" : "=l"(r) : "r"(u));
    return r;
}
__device__ __forceinline__ float hsum2(unsigned long long a) {
    unsigned lo, hi;
    asm("mov.b64 {%0, %1}, %2;" : "=r"(lo), "=r"(hi) : "l"(a));
    return __uint_as_float(lo) + __uint_as_float(hi);
}

// ---------------------------------------------------------------------------
// Phase 1: xz = emb[text] @ [W_f|W_b] + bias.  M=32768, N=2048, K=128
// ---------------------------------------------------------------------------
__global__ __launch_bounds__(256) void gemm_xz_kernel(
    const int* __restrict__ text, const float* __restrict__ emb,
    const float* __restrict__ Wf, const float* __restrict__ Wb,
    const float* __restrict__ bf, const float* __restrict__ bb)
{
    __shared__ float As[16][128];
    __shared__ float Ws[16][64];
    __shared__ int   toks[128];

    const int m0 = blockIdx.y * 128;
    const int n0 = blockIdx.x * 64;
    const int tid = threadIdx.x;

    if (tid < 128) toks[tid] = text[m0 + tid];
    __syncthreads();

    const float* W = (n0 < H4) ? Wf : Wb;
    const int nw0 = n0 & (H4 - 1);
    const int tx = tid & 15;
    const int ty = tid >> 4;

    unsigned long long acc2[4][4];   // row-pair x col, packed f32x2
#pragma unroll
    for (int i = 0; i < 4; i++)
#pragma unroll
        for (int j = 0; j < 4; j++) acc2[i][j] = 0ull;

    for (int k0 = 0; k0 < EMB; k0 += 16) {
#pragma unroll
        for (int q = 0; q < 2; q++) {
            int id = tid * 2 + q;
            int row = id >> 2, kq = id & 3;
            float4 v = *reinterpret_cast<const float4*>(&emb[toks[row] * EMB + k0 + kq * 4]);
            As[kq * 4 + 0][row] = v.x;
            As[kq * 4 + 1][row] = v.y;
            As[kq * 4 + 2][row] = v.z;
            As[kq * 4 + 3][row] = v.w;
        }
        {
            int k = tid >> 4, n4 = (tid & 15) * 4;
            *reinterpret_cast<float4*>(&Ws[k][n4]) =
                *reinterpret_cast<const float4*>(&W[(k0 + k) * H4 + nw0 + n4]);
        }
        __syncthreads();

#pragma unroll
        for (int k = 0; k < 16; k++) {
            ulonglong2 a01 = *reinterpret_cast<const ulonglong2*>(&As[k][ty * 8]);
            ulonglong2 a23 = *reinterpret_cast<const ulonglong2*>(&As[k][ty * 8 + 4]);
            float4 w4 = *reinterpret_cast<const float4*>(&Ws[k][tx * 4]);
            unsigned long long ap[4] = {a01.x, a01.y, a23.x, a23.y};
            unsigned long long wd[4] = {dupf2(w4.x), dupf2(w4.y), dupf2(w4.z), dupf2(w4.w)};
#pragma unroll
            for (int i = 0; i < 4; i++)
#pragma unroll
                for (int j = 0; j < 4; j++) fma2(acc2[i][j], ap[i], wd[j]);
        }
        __syncthreads();
    }

    const float* bias = (n0 < H4) ? bf : bb;
    const int d = (n0 < H4) ? 0 : 1;
    const int col = nw0 + tx * 4;
    float4 bv = *reinterpret_cast<const float4*>(&bias[col]);

#pragma unroll
    for (int i = 0; i < 4; i++) {
#pragma unroll
        for (int half = 0; half < 2; half++) {
            int gm = m0 + ty * 8 + 2 * i + half;
            int b = gm >> 9, t = gm & (SEQ - 1);
            float4 v;
            unsigned lo, hi;
            asm("mov.b64 {%0, %1}, %2;" : "=r"(lo), "=r"(hi) : "l"(acc2[i][0]));
            v.x = __uint_as_float(half ? hi : lo) + bv.x;
            asm("mov.b64 {%0, %1}, %2;" : "=r"(lo), "=r"(hi) : "l"(acc2[i][1]));
            v.y = __uint_as_float(half ? hi : lo) + bv.y;
            asm("mov.b64 {%0, %1}, %2;" : "=r"(lo), "=r"(hi) : "l"(acc2[i][2]));
            v.z = __uint_as_float(half ? hi : lo) + bv.z;
            asm("mov.b64 {%0, %1}, %2;" : "=r"(lo), "=r"(hi) : "l"(acc2[i][3]));
            v.w = __uint_as_float(half ? hi : lo) + bv.w;
            *reinterpret_cast<float4*>(&g_xz[d][t][b][col]) = v;
        }
    }
}

// ---------------------------------------------------------------------------
// Phase 2: persistent bidirectional LSTM. 16 clusters x 8 CTAs (128 SMs).
// cluster = (dir, batch-block of 8 rows); rank cb = 32-unit column block.
// Warp = 32 gate-columns x one K-half; h exchanged via DSMEM push.
// ---------------------------------------------------------------------------
#define UT_PAD 260
#define LSTM_SMEM ((128 * UT_PAD + 2 * 8 * 256 + 2 * 8 * 128) * 4)

__global__ void __cluster_dims__(8, 1, 1) __launch_bounds__(256, 1)
lstm_kernel(const float* __restrict__ Uf, const float* __restrict__ Ub)
{
    extern __shared__ float smem[];
    float* Ut  = smem;                  // [128][UT_PAD] transposed U slice
    float* hsh = Ut + 128 * UT_PAD;     // [2][8][256]  double-buffered h
    float* zsh = hsh + 2 * 8 * 256;     // [2][8][128]  z partials per K-half

    const int tid = threadIdx.x;
    const int cb  = blockIdx.x & 7;     // cluster rank = column block
    const int cid = blockIdx.x >> 3;
    const int d   = cid >> 3;           // direction
    const int bb  = cid & 7;            // batch block
    const float* U = d ? Ub : Uf;

    // resident transposed U slice: Ut[c][k] = U[k][gate(c)*256 + cb*32 + unit(c)]
    for (int i = tid; i < 128 * 256; i += 256) {
        int c = i & 127, k = i >> 7;
        int gcol = ((c >> 5) << 8) + (cb << 5) + (c & 31);
        Ut[c * UT_PAD + k] = U[k * H4 + gcol];
    }
    for (int i = tid; i < 2 * 8 * 256; i += 256) hsh[i] = 0.0f;
    __syncthreads();
    asm volatile("barrier.cluster.arrive.aligned;" ::: "memory");
    asm volatile("barrier.cluster.wait.aligned;" ::: "memory");

    const int w = tid >> 5, lane = tid & 31;
    const int kh = w >> 2;                       // K-half (0/1)
    const int c  = ((w & 3) << 5) + lane;        // gate column 0..127
    const float* UtC = &Ut[c * UT_PAD + kh * 128];

    const int rB = tid >> 5;                     // gate-phase row
    const int uB = lane;                         // gate-phase unit-in-block
    const int bglob = bb * 8 + rB;
    const unsigned hbase = (unsigned)__cvta_generic_to_shared(hsh);
    float cell = 0.0f;
    int cur = 0;

    for (int t = 0; t < SEQ; t++) {
        const int tt = d ? (SEQ - 1 - t) : t;

        // prefetch xz for this thread's 4 gates (consumed after GEMM)
        const float* xzp = &g_xz[d][tt][bglob][(cb << 5) + uB];
        const float xi = __ldg(xzp);
        const float xf = __ldg(xzp + 256);
        const float xg = __ldg(xzp + 512);
        const float xo = __ldg(xzp + 768);

        // GEMM: partial z[r][c] over K-half kh, r = 0..7, packed f32x2
        unsigned long long acc[8];
#pragma unroll
        for (int r = 0; r < 8; r++) acc[r] = 0ull;
        const float* hp = &hsh[cur * 2048 + kh * 128];
#pragma unroll 2
        for (int k4 = 0; k4 < 32; k4++) {
            ulonglong2 u2 = *reinterpret_cast<const ulonglong2*>(&UtC[k4 * 4]);
#pragma unroll
            for (int r = 0; r < 8; r++) {
                ulonglong2 h2 = *reinterpret_cast<const ulonglong2*>(&hp[r * 256 + k4 * 4]);
                fma2(acc[r], u2.x, h2.x);
                fma2(acc[r], u2.y, h2.y);
            }
        }
#pragma unroll
        for (int r = 0; r < 8; r++)
            zsh[(kh * 8 + r) * 128 + c] = hsum2(acc[r]);
        __syncthreads();

        // gates: thread -> (row rB, unit uB)
        const float zi = zsh[rB * 128 +  0 + uB] + zsh[(8 + rB) * 128 +  0 + uB] + xi;
        const float zf = zsh[rB * 128 + 32 + uB] + zsh[(8 + rB) * 128 + 32 + uB] + xf;
        const float zg = zsh[rB * 128 + 64 + uB] + zsh[(8 + rB) * 128 + 64 + uB] + xg;
        const float zo = zsh[rB * 128 + 96 + uB] + zsh[(8 + rB) * 128 + 96 + uB] + xo;
        const float ig = sigmoid_f(zi);
        const float fg = sigmoid_f(zf);
        const float gg = tanh_f(zg);
        const float og = sigmoid_f(zo);
        cell = fg * cell + ig * gg;
        const float h = og * tanh_f(cell);

        // push h to all 8 cluster CTAs' next buffer via DSMEM
        const int nxt = cur ^ 1;
        const unsigned off = hbase + (unsigned)(((nxt * 8 + rB) * 256 + (cb << 5) + uB) * 4);
#pragma unroll
        for (int p = 0; p < 8; p++) {
            asm volatile(
                "{ .reg .b32 r; mapa.shared::cluster.u32 r, %0, %1;"
                "  st.shared::cluster.f32 [r], %2; }"
                :: "r"(off), "r"(p), "f"(h) : "memory");
        }
        g_hall[(bglob * SEQ + tt) * (2 * HID) + d * HID + (cb << 5) + uB] = h;

        asm volatile("barrier.cluster.arrive.aligned;" ::: "memory");
        asm volatile("barrier.cluster.wait.aligned;" ::: "memory");
        cur = nxt;
    }
}

// ---------------------------------------------------------------------------
// Phase 3: logits = h_all @ W_d + b_d   (warp per row-group)
// ---------------------------------------------------------------------------
__global__ __launch_bounds__(256) void decoder_kernel(
    const float* __restrict__ Wd, const float* __restrict__ bd,
    float* __restrict__ out)
{
    __shared__ float Ws[2 * HID * TAGS];
    __shared__ float bs[TAGS];
    const int tid = threadIdx.x;
    for (int i = tid; i < 2 * HID * TAGS; i += 256) Ws[i] = Wd[i];
    if (tid < TAGS) bs[tid] = bd[tid];
    __syncthreads();

    const int w = tid >> 5, lane = tid & 31;
    const int wg = blockIdx.x * 8 + w;

    for (int rr = 0; rr < 16; rr++) {
        const int row = wg * 16 + rr;
        const float* hp = &g_hall[row * (2 * HID)];
        float p[TAGS];
#pragma unroll
        for (int j = 0; j < TAGS; j++) p[j] = 0.0f;
#pragma unroll
        for (int e = 0; e < 16; e++) {
            const int k = e * 32 + lane;
            const float hv = __ldg(&hp[k]);
#pragma unroll
            for (int j = 0; j < TAGS; j++) p[j] += hv * Ws[k * TAGS + j];
        }
#pragma unroll
        for (int j = 0; j < TAGS; j++)
#pragma unroll
            for (int off = 16; off; off >>= 1)
                p[j] += __shfl_xor_sync(0xffffffffu, p[j], off);
        if (lane < TAGS) out[row * TAGS + lane] = p[lane] + bs[lane];
    }
}

// ---------------------------------------------------------------------------
// Phase 4: lens + CRF sequence score + log-norm. One warp per batch row.
// ---------------------------------------------------------------------------
__global__ __launch_bounds__(32) void crf_kernel(
    const int* __restrict__ text, const int* __restrict__ labels,
    const float* __restrict__ trans, const float* __restrict__ logits,
    float* __restrict__ out_lens, float* __restrict__ out_ll)
{
    __shared__ float lg[SEQ * TAGS];
    __shared__ int   lb[SEQ];
    __shared__ float tr[TAGS * TAGS];

    const int b = blockIdx.x;
    const int lane = threadIdx.x;
    const float* Lp = logits + b * SEQ * TAGS;

    for (int i = lane; i < SEQ * TAGS; i += 32) lg[i] = Lp[i];
    for (int i = lane; i < SEQ; i += 32) lb[i] = labels[b * SEQ + i];
    for (int i = lane; i < TAGS * TAGS; i += 32) tr[i] = trans[i];

    int cnt = 0;
    for (int t = lane; t < SEQ; t += 32) cnt += (text[b * SEQ + t] != 0);
#pragma unroll
    for (int off = 16; off; off >>= 1) cnt += __shfl_xor_sync(0xffffffffu, cnt, off);
    __syncthreads();
    const int len = cnt;

    float uny = 0.0f, bny = 0.0f;
    for (int t = lane; t < SEQ; t += 32)
        if (t < len) uny += lg[t * TAGS + lb[t]];
    for (int t = lane; t < SEQ - 1; t += 32)
        if (t < len - 1) bny += tr[lb[t] * TAGS + lb[t + 1]];
#pragma unroll
    for (int off = 16; off; off >>= 1) {
        uny += __shfl_xor_sync(0xffffffffu, uny, off);
        bny += __shfl_xor_sync(0xffffffffu, bny, off);
    }

    // forward algorithm; tag j = lane (lanes >= TAGS mirror j=TAGS-1)
    const int j = (lane < TAGS) ? lane : (TAGS - 1);
    float Tc[TAGS];
#pragma unroll
    for (int i = 0; i < TAGS; i++) Tc[i] = tr[i * TAGS + j];

    float a = lg[j];
    for (int t = 1; t < SEQ; t++) {
        float ai[TAGS];
#pragma unroll
        for (int i = 0; i < TAGS; i++) ai[i] = __shfl_sync(0xffffffffu, a, i);
        if (t < len) {
            float m = -1e30f;
#pragma unroll
            for (int i = 0; i < TAGS; i++) m = fmaxf(m, ai[i] + Tc[i]);
            float s = 0.0f;
#pragma unroll
            for (int i = 0; i < TAGS; i++) s += __expf(ai[i] + Tc[i] - m);
            a = m + __logf(s) + lg[t * TAGS + j];
        }
    }
    float av = (lane < TAGS) ? a : -1e30f;
    float m = av;
#pragma unroll
    for (int off = 16; off; off >>= 1) m = fmaxf(m, __shfl_xor_sync(0xffffffffu, m, off));
    float s = (lane < TAGS) ? __expf(av - m) : 0.0f;
#pragma unroll
    for (int off = 16; off; off >>= 1) s += __shfl_xor_sync(0xffffffffu, s, off);
    const float logZ = m + __logf(s);

    if (lane == 0) {
        out_lens[b] = (float)len;
        out_ll[b]   = uny + bny - logZ;
    }
}

// ---------------------------------------------------------------------------
extern "C" void kernel_launch(void* const* d_in, const int* in_sizes, int n_in,
                              void* d_out, int out_size) {
    const int*   text   = (const int*)  d_in[0];
    const int*   labels = (const int*)  d_in[1];
    const float* emb    = (const float*)d_in[2];
    const float* W_f    = (const float*)d_in[3];
    const float* U_f    = (const float*)d_in[4];
    const float* b_f    = (const float*)d_in[5];
    const float* W_b    = (const float*)d_in[6];
    const float* U_b    = (const float*)d_in[7];
    const float* b_b    = (const float*)d_in[8];
    const float* W_d    = (const float*)d_in[9];
    const float* b_d    = (const float*)d_in[10];
    const float* trans  = (const float*)d_in[11];
    float* out = (float*)d_out;

    static bool attr_done = false;
    if (!attr_done) {
        cudaFuncSetAttribute(lstm_kernel,
                             cudaFuncAttributeMaxDynamicSharedMemorySize, LSTM_SMEM);
        attr_done = true;
    }

    gemm_xz_kernel<<<dim3(32, 256), 256>>>(text, emb, W_f, W_b, b_f, b_b);
    lstm_kernel<<<128, 256, LSTM_SMEM>>>(U_f, U_b);
    decoder_kernel<<<256, 256>>>(W_d, b_d, out);

    float* out_logits = out;                         // B*S*TAGS
    float* out_lens   = out + BATCH * SEQ * TAGS;    // 64
    float* out_ll     = out_lens + BATCH;            // 64
    crf_kernel<<<BATCH, 32>>>(text, labels, trans, out_logits, out_lens, out_ll);
}